// round 7
// baseline (speedup 1.0000x reference)
#include <cuda_runtime.h>

// N = 2,000,000 rows. Elementwise Gaussian-splat covariance projection.
// Inputs: rot (N,4) f32, mod (1,) f32, scale (N,2) f32, p_k (N,3) f32,
//         view_matrix (N,16) f32.  Output: A (N,9) f32.
//
// R3: ALL wide/strided traffic staged through smem as coalesced float4:
//   - vm (stride-64B per-thread loads were 4x wavefront-inefficient)
//   - p_k (stride-12B)
//   - out (stride-36B)
// rot (16B) and scale (8B) per-thread loads are already wavefront-optimal.

#define TPB 256
#define RPB 256
#define VMP 17                      // padded vm row stride (odd -> conflict-free)

__global__ __launch_bounds__(TPB)
void splat_cov_kernel(const float4* __restrict__ rot,       // (N,4) as float4
                      const float*  __restrict__ mod,       // (1,)
                      const float2* __restrict__ scale,     // (N,2) as float2
                      const float*  __restrict__ p_k,       // (N,3)
                      const float4* __restrict__ vm4,       // (N,16) as 4x float4
                      float*        __restrict__ out,       // (N,9)
                      int n)
{
    __shared__ float s_vm[RPB * VMP];   // 17.4 KB, padded
    __shared__ float s_p[RPB * 3];      //  3.0 KB
    __shared__ float s_o[RPB * 9];      //  9.2 KB

    const int block_base = blockIdx.x * RPB;
    const int rows = min(RPB, n - block_base);

    // ---- Stage vm cooperatively: coalesced LDG.128, padded smem rows ----
    {
        const float4* src = vm4 + (size_t)block_base * 4;
        const int nvec = rows * 4;                    // up to 1024 float4s
        #pragma unroll 4
        for (int t = threadIdx.x; t < nvec; t += TPB) {
            float4 v = __ldcs(&src[t]);
            float* d = s_vm + (t >> 2) * VMP + (t & 3) * 4;
            d[0] = v.x; d[1] = v.y; d[2] = v.z; d[3] = v.w;
        }
    }

    // ---- Stage p_k cooperatively ----
    {
        const int nfloat = rows * 3;
        const float4* src = (const float4*)(p_k + (size_t)block_base * 3);
        float4* dst = (float4*)s_p;
        const int nvec = nfloat >> 2;
        for (int t = threadIdx.x; t < nvec; t += TPB) dst[t] = __ldcs(&src[t]);
        for (int t = (nvec << 2) + threadIdx.x; t < nfloat; t += TPB)
            s_p[t] = p_k[(size_t)block_base * 3 + t];
    }

    const float m = __ldg(mod);
    const int i = block_base + threadIdx.x;

    // rot / scale: per-thread coalesced loads, issue before barrier for overlap
    float4 q = make_float4(0.f, 0.f, 0.f, 0.f);
    float2 sc = make_float2(0.f, 0.f);
    if (i < n) {
        q  = __ldcs(&rot[i]);
        sc = __ldcs(&scale[i]);
    }

    __syncthreads();

    if (i < n) {
        float r = q.x, x = q.y, y = q.z, z = q.w;

        float R00 = 1.0f - 2.0f * (y * y + z * z);
        float R10 = 2.0f * (x * y + r * z);
        float R20 = 2.0f * (x * z - r * y);
        float R01 = 2.0f * (x * y - r * z);
        float R11 = 1.0f - 2.0f * (x * x + z * z);
        float R21 = 2.0f * (y * z + r * x);

        float s0 = m * sc.x;
        float s1 = m * sc.y;

        float u0 = s0 * R00, u1 = s0 * R10, u2 = s0 * R20;
        float v0 = s1 * R01, v1 = s1 * R11, v2 = s1 * R21;

        const float* v = s_vm + threadIdx.x * VMP;    // conflict-free (stride 17)
        float m00 = v[0],  m01 = v[1],  m02 = v[2];
        float m40 = v[4],  m41 = v[5],  m42 = v[6];
        float m80 = v[8],  m81 = v[9],  m82 = v[10];
        float mc0 = v[12], mc1 = v[13], mc2 = v[14];

        float p0 = s_p[threadIdx.x * 3 + 0];
        float p1 = s_p[threadIdx.x * 3 + 1];
        float p2 = s_p[threadIdx.x * 3 + 2];

        float r1s1 = m00 * u0 + m40 * u1 + m80 * u2;
        float r1s2 = m00 * v0 + m40 * v1 + m80 * v2;
        float r2s1 = m01 * u0 + m41 * u1 + m81 * u2;
        float r2s2 = m01 * v0 + m41 * v1 + m81 * v2;
        float r3s1 = m02 * u0 + m42 * u1 + m82 * u2;
        float r3s2 = m02 * v0 + m42 * v1 + m82 * v2;

        float r1p = m00 * p0 + m40 * p1 + m80 * p2 + mc0;
        float r2p = m01 * p0 + m41 * p1 + m81 * p2 + mc1;
        float r3p = m02 * p0 + m42 * p1 + m82 * p2 + mc2;

        float* o = s_o + threadIdx.x * 9;             // odd stride: conflict-free
        o[0] = r1s1;
        o[1] = r1s2;
        o[2] = r1p;
        o[3] = r2s1;
        o[4] = r2s2;
        o[5] = r2p;
        o[6] = r3s1;
        o[7] = r3s2;
        o[8] = r3p;
    }

    __syncthreads();

    // ---- Store cooperatively: coalesced float4 streaming stores ----
    {
        const int nfloat = rows * 9;                  // up to 2304
        const size_t out_base = (size_t)block_base * 9;  // 2304*blockIdx -> aligned
        float4* dst = (float4*)(out + out_base);
        const float4* src = (const float4*)s_o;
        const int nvec = nfloat >> 2;                 // up to 576
        #pragma unroll 2
        for (int t = threadIdx.x; t < nvec; t += TPB) __stcs(&dst[t], src[t]);
        for (int t = (nvec << 2) + threadIdx.x; t < nfloat; t += TPB)
            out[out_base + t] = s_o[t];
    }
}

extern "C" void kernel_launch(void* const* d_in, const int* in_sizes, int n_in,
                              void* d_out, int out_size)
{
    const float4* rot   = (const float4*)d_in[0];
    const float*  mod   = (const float*)d_in[1];
    const float2* scale = (const float2*)d_in[2];
    const float*  p_k   = (const float*)d_in[3];
    const float4* vm4   = (const float4*)d_in[4];
    float* out = (float*)d_out;

    int n = in_sizes[0] / 4;   // rot has N*4 elements

    int blocks = (n + RPB - 1) / RPB;
    splat_cov_kernel<<<blocks, TPB>>>(rot, mod, scale, p_k, vm4, out, n);
}